// round 3
// baseline (speedup 1.0000x reference)
#include <cuda_runtime.h>

#define T_ 12
#define N_ 10000
#define F_ 128
#define H_ 128
#define E_ 320000
#define NH (N_*H_)

// ---------------- scratch (static device memory; no runtime allocation) ----------------
__device__ __align__(16) float g_Tx1[NH];
__device__ __align__(16) float g_Tx2[NH];
__device__ __align__(16) float g_Th1[NH];
__device__ __align__(16) float g_Th2[NH];
__device__ __align__(16) float g_Ts1[NH];
__device__ __align__(16) float g_Ts2[NH];
__device__ __align__(16) float g_h  [NH];
__device__ __align__(16) float g_z  [NH];
__device__ __align__(16) float g_s  [NH];
__device__ float g_deg[N_];       // degree, then dinv in-place
__device__ int   g_cnt[N_];       // per-dst edge count
__device__ int   g_rowptr[N_ + 1];
__device__ int   g_pos[E_];
__device__ int   g_col[E_];       // CSR: src node per edge, grouped by dst
__device__ float g_val[E_];       // CSR: norm value per edge
__device__ int   g_is64;          // 1 if edge_index is int64, 0 if int32

// Edge accessor: dtype decided at runtime via g_is64.
__device__ __forceinline__ int edge_at(const void* ei, int idx) {
    if (g_is64) return (int)((const long long*)ei)[idx];
    return ((const int*)ei)[idx];
}

// ---------------- preprocessing kernels ----------------
// Detect int64 vs int32 layout: int64 values < 2^32 read as int32 pairs (v, 0),
// so all odd-index words zero over a 1024-word sample <=> int64.
__global__ void k_dtype(const int* __restrict__ ei32) {
    if (threadIdx.x == 0) {
        int any_odd_nonzero = 0;
        for (int i = 1; i < 1024; i += 2) any_odd_nonzero |= (ei32[i] != 0);
        g_is64 = any_odd_nonzero ? 0 : 1;
    }
}

__global__ void k_init() {
    int i = blockIdx.x * blockDim.x + threadIdx.x;
    if (i < NH) g_h[i] = 0.f;
    if (i < N_) { g_deg[i] = 0.f; g_cnt[i] = 0; }
}

__global__ void k_count(const void* __restrict__ ei) {
    int e = blockIdx.x * blockDim.x + threadIdx.x;
    if (e >= E_) return;
    int s = edge_at(ei, e);
    int d = edge_at(ei, E_ + e);
    if ((unsigned)s >= N_ || (unsigned)d >= N_) return;  // safety net
    atomicAdd(&g_deg[s], 1.0f);              // src-based degree (matches reference)
    g_pos[e] = atomicAdd(&g_cnt[d], 1);      // slot within dst bucket
}

__global__ void k_dinv() {
    int i = blockIdx.x * blockDim.x + threadIdx.x;
    if (i >= N_) return;
    float d = g_deg[i];
    g_deg[i] = (d > 0.f) ? rsqrtf(d) : 0.f;
}

// exclusive prefix sum of g_cnt -> g_rowptr, single block of 1024 threads
__global__ void k_scan() {
    __shared__ int sh[1024];
    int tid = threadIdx.x;
    const int PER = (N_ + 1023) / 1024;      // 10
    int base = tid * PER;
    int s = 0;
    for (int i = 0; i < PER; i++) { int ix = base + i; if (ix < N_) s += g_cnt[ix]; }
    sh[tid] = s;
    __syncthreads();
    for (int off = 1; off < 1024; off <<= 1) {
        int v = (tid >= off) ? sh[tid - off] : 0;
        __syncthreads();
        if (tid >= off) sh[tid] += v;
        __syncthreads();
    }
    int run = (tid > 0) ? sh[tid - 1] : 0;
    for (int i = 0; i < PER; i++) {
        int ix = base + i;
        if (ix < N_) { g_rowptr[ix] = run; run += g_cnt[ix]; }
    }
    if (tid == 0) g_rowptr[N_] = sh[1023];
}

__global__ void k_fill(const void* __restrict__ ei) {
    int e = blockIdx.x * blockDim.x + threadIdx.x;
    if (e >= E_) return;
    int s = edge_at(ei, e);
    int d = edge_at(ei, E_ + e);
    if ((unsigned)s >= N_ || (unsigned)d >= N_) return;  // safety net
    int slot = g_rowptr[d] + g_pos[e];
    g_col[slot] = s;
    g_val[slot] = -g_deg[s] * g_deg[d];      // g_deg holds dinv here
}

// ---------------- graph propagation (dual): out[n] = scale*sum_e val*in[col] - sub[n] ----------------
// blockIdx.y selects one of two independent (in,out,sub) problems; one block per dst
// node; 128 threads = one feature column each; gather-reduce, no atomics.
__global__ void k_prop2(const float* __restrict__ in0, float* __restrict__ out0,
                        const float* __restrict__ sub0,
                        const float* __restrict__ in1, float* __restrict__ out1,
                        const float* __restrict__ sub1, float scale) {
    const float* in  = blockIdx.y ? in1  : in0;
    float*       out = blockIdx.y ? out1 : out0;
    const float* sub = blockIdx.y ? sub1 : sub0;
    if (!in) return;
    int n = blockIdx.x;
    int j = threadIdx.x;
    int e = g_rowptr[n], end = g_rowptr[n + 1];
    float a0 = 0.f, a1 = 0.f, a2 = 0.f, a3 = 0.f;
    for (; e + 4 <= end; e += 4) {
        int   c0 = g_col[e],     c1 = g_col[e + 1], c2 = g_col[e + 2], c3 = g_col[e + 3];
        float w0 = g_val[e],     w1 = g_val[e + 1], w2 = g_val[e + 2], w3 = g_val[e + 3];
        a0 += w0 * __ldg(in + c0 * H_ + j);
        a1 += w1 * __ldg(in + c1 * H_ + j);
        a2 += w2 * __ldg(in + c2 * H_ + j);
        a3 += w3 * __ldg(in + c3 * H_ + j);
    }
    float acc = (a0 + a1) + (a2 + a3);
    for (; e < end; e++) acc += g_val[e] * __ldg(in + g_col[e] * H_ + j);
    float r = scale * acc;
    if (sub) r -= sub[n * H_ + j];
    out[n * H_ + j] = r;
}

// ---------------- multi-pair GEMM with fused GRU epilogues ----------------
// C[N x 128] = sum_{p=0..5} A_p[N x 128] @ B_p[128 x 128] + b0 + b1, then epilogue:
//   mode 0: out = sigmoid(v)                        (z gate)
//   mode 1: out = h * sigmoid(v)                    (s = h*r)
//   mode 2: out = z*h + (1-z)*tanh(v)               (GRU state update, in-place on h)
struct GP {
    const float* A[6];
    const float* B[6];
    const float* b0;
    const float* b1;
    const float* h;
    const float* z;
    float* out;
};

__device__ __forceinline__ float sigf(float x) { return 1.f / (1.f + expf(-x)); }

__global__ __launch_bounds__(256) void k_gemm(GP p0, GP p1, int m0, int m1) {
    const GP& P   = (blockIdx.y == 0) ? p0 : p1;
    const int mode = (blockIdx.y == 0) ? m0 : m1;

    __shared__ float  As[32][17];     // padded to kill store conflicts
    __shared__ float4 Bs[16][32];     // 16 x 128 floats

    const int tid  = threadIdx.x;
    const int bm   = blockIdx.x * 32;
    const int arow = tid >> 3;            // 0..31
    const int ac0  = (tid & 7) * 2;       // 0..14
    const int brow = tid >> 5;            // 0..7
    const int bcol = tid & 31;            // float4 column
    const int ttx  = tid & 15;            // col group (8 cols each)
    const int trow = (tid >> 4) * 2;      // row pair
    const bool aok = (bm + arow) < N_;
    const int aoff = (bm + arow) * H_ + ac0;

    float acc[2][8];
#pragma unroll
    for (int i = 0; i < 2; i++)
#pragma unroll
        for (int j = 0; j < 8; j++) acc[i][j] = 0.f;

    float2 ra;
    float4 rb0, rb1;
    {   // prefetch tile 0 (pair 0, ktile 0)
        const float* Ap = P.A[0];
        ra  = aok ? *(const float2*)(Ap + aoff) : make_float2(0.f, 0.f);
        const float* Bp = P.B[0];
        rb0 = *(const float4*)(Bp + brow * H_ + bcol * 4);
        rb1 = *(const float4*)(Bp + (brow + 8) * H_ + bcol * 4);
    }
    As[arow][ac0] = ra.x; As[arow][ac0 + 1] = ra.y;
    Bs[brow][bcol] = rb0; Bs[brow + 8][bcol] = rb1;
    __syncthreads();

#pragma unroll 1
    for (int t = 0; t < 48; t++) {        // 6 pairs x 8 k-tiles of 16
        if (t + 1 < 48) {
            int p = (t + 1) >> 3, kb = (t + 1) & 7;
            const float* Ap = P.A[p];
            ra  = aok ? *(const float2*)(Ap + aoff + kb * 16) : make_float2(0.f, 0.f);
            const float* Bp = P.B[p];
            rb0 = *(const float4*)(Bp + (kb * 16 + brow) * H_ + bcol * 4);
            rb1 = *(const float4*)(Bp + (kb * 16 + brow + 8) * H_ + bcol * 4);
        }
#pragma unroll
        for (int k = 0; k < 16; k++) {
            float  a0 = As[trow][k], a1 = As[trow + 1][k];
            float4 b0 = Bs[k][ttx * 2], b1 = Bs[k][ttx * 2 + 1];
            acc[0][0] += a0 * b0.x; acc[0][1] += a0 * b0.y;
            acc[0][2] += a0 * b0.z; acc[0][3] += a0 * b0.w;
            acc[0][4] += a0 * b1.x; acc[0][5] += a0 * b1.y;
            acc[0][6] += a0 * b1.z; acc[0][7] += a0 * b1.w;
            acc[1][0] += a1 * b0.x; acc[1][1] += a1 * b0.y;
            acc[1][2] += a1 * b0.z; acc[1][3] += a1 * b0.w;
            acc[1][4] += a1 * b1.x; acc[1][5] += a1 * b1.y;
            acc[1][6] += a1 * b1.z; acc[1][7] += a1 * b1.w;
        }
        __syncthreads();
        if (t + 1 < 48) {
            As[arow][ac0] = ra.x; As[arow][ac0 + 1] = ra.y;
            Bs[brow][bcol] = rb0; Bs[brow + 8][bcol] = rb1;
        }
        __syncthreads();
    }

#pragma unroll
    for (int i = 0; i < 2; i++) {
        int row = bm + trow + i;
        if (row < N_) {
#pragma unroll
            for (int j = 0; j < 8; j++) {
                int col = ttx * 8 + j;
                float v = acc[i][j] + P.b0[col] + P.b1[col];
                int idx = row * H_ + col;
                float o;
                if (mode == 0)      o = sigf(v);
                else if (mode == 1) o = P.h[idx] * sigf(v);
                else { float zz = P.z[idx]; o = zz * P.h[idx] + (1.f - zz) * tanhf(v); }
                P.out[idx] = o;
            }
        }
    }
}

// ---------------- output projection: out[n] = dot(h[n,:], Wl) + bl ----------------
__global__ void k_proj(const float* __restrict__ h, const float* __restrict__ Wl,
                       const float* __restrict__ bl, float* __restrict__ out) {
    int n = blockIdx.x * 8 + (threadIdx.x >> 5);
    if (n >= N_) return;
    int lane = threadIdx.x & 31;
    float4 a = *(const float4*)(h + n * H_ + lane * 4);
    float4 w = *(const float4*)(Wl + lane * 4);
    float s = a.x * w.x + a.y * w.y + a.z * w.z + a.w * w.w;
#pragma unroll
    for (int o = 16; o; o >>= 1) s += __shfl_down_sync(0xffffffffu, s, o);
    if (lane == 0) out[n] = s + bl[0];
}

// ---------------- driver ----------------
extern "C" void kernel_launch(void* const* d_in, const int* in_sizes, int n_in,
                              void* d_out, int out_size) {
    const float* x_seq = (const float*)d_in[0];
    const void*  ei    = d_in[1];                    // int32 or int64, detected on device
    const float* Wxz = (const float*)d_in[2];  const float* bxz = (const float*)d_in[3];
    const float* Whz = (const float*)d_in[4];  const float* bhz = (const float*)d_in[5];
    const float* Wxr = (const float*)d_in[6];  const float* bxr = (const float*)d_in[7];
    const float* Whr = (const float*)d_in[8];  const float* bhr = (const float*)d_in[9];
    const float* Wxh = (const float*)d_in[10]; const float* bxh = (const float*)d_in[11];
    const float* Whh = (const float*)d_in[12]; const float* bhh = (const float*)d_in[13];
    const float* Wl  = (const float*)d_in[14]; const float* bl  = (const float*)d_in[15];
    float* out = (float*)d_out;

    float *Tx1, *Tx2, *Th1, *Th2, *Ts1, *Ts2, *h, *z, *s;
    cudaGetSymbolAddress((void**)&Tx1, g_Tx1);
    cudaGetSymbolAddress((void**)&Tx2, g_Tx2);
    cudaGetSymbolAddress((void**)&Th1, g_Th1);
    cudaGetSymbolAddress((void**)&Th2, g_Th2);
    cudaGetSymbolAddress((void**)&Ts1, g_Ts1);
    cudaGetSymbolAddress((void**)&Ts2, g_Ts2);
    cudaGetSymbolAddress((void**)&h,   g_h);
    cudaGetSymbolAddress((void**)&z,   g_z);
    cudaGetSymbolAddress((void**)&s,   g_s);

    // preprocessing: dtype detect, zero state, degree norm + dst-CSR
    k_dtype<<<1, 32>>>((const int*)ei);
    k_init <<<(NH + 255) / 256, 256>>>();
    k_count<<<(E_ + 255) / 256, 256>>>(ei);
    k_dinv <<<(N_ + 255) / 256, 256>>>();
    k_scan <<<1, 1024>>>();
    k_fill <<<(E_ + 255) / 256, 256>>>(ei);

    const int WK = F_ * H_;               // 16384 floats per K-slice of a weight tensor
    const int GB = (N_ + 31) / 32;        // 313 row tiles

    for (int t = 0; t < T_; t++) {
        const float* xt = x_seq + (size_t)t * N_ * F_;

        // Chebyshev chains (x and h fused per hop):
        //   Tx1 = L x ; Th1 = L h         (hop 1, 2 problems in one launch)
        //   Tx2 = 2 L Tx1 - x ; Th2 = 2 L Th1 - h
        k_prop2<<<dim3(N_, 2), H_>>>(xt,  Tx1, nullptr, h,   Th1, nullptr, 1.f);
        k_prop2<<<dim3(N_, 2), H_>>>(Tx1, Tx2, xt,      Th1, Th2, h,       2.f);

        GP pz, pr, ph;
        const float* Axs[6] = { xt, Tx1, Tx2, h, Th1, Th2 };
        for (int i = 0; i < 6; i++) { pz.A[i] = Axs[i]; pr.A[i] = Axs[i]; }
        for (int k = 0; k < 3; k++) {
            pz.B[k] = Wxz + k * WK; pz.B[3 + k] = Whz + k * WK;
            pr.B[k] = Wxr + k * WK; pr.B[3 + k] = Whr + k * WK;
        }
        pz.b0 = bxz; pz.b1 = bhz; pz.out = z; pz.h = nullptr; pz.z = nullptr;
        pr.b0 = bxr; pr.b1 = bhr; pr.out = s; pr.h = h;       pr.z = nullptr;
        // z = sigmoid(...), s = h * sigmoid(...) in one 626-block launch
        k_gemm<<<dim3(GB, 2), 256>>>(pz, pr, 0, 1);

        // Chebyshev chain on s = h*r
        k_prop2<<<dim3(N_, 1), H_>>>(s,   Ts1, nullptr, nullptr, nullptr, nullptr, 1.f);
        k_prop2<<<dim3(N_, 1), H_>>>(Ts1, Ts2, s,       nullptr, nullptr, nullptr, 2.f);

        const float* Ahs[6] = { xt, Tx1, Tx2, s, Ts1, Ts2 };
        for (int i = 0; i < 6; i++) ph.A[i] = Ahs[i];
        for (int k = 0; k < 3; k++) { ph.B[k] = Wxh + k * WK; ph.B[3 + k] = Whh + k * WK; }
        ph.b0 = bxh; ph.b1 = bhh; ph.out = h; ph.h = h; ph.z = z;
        // h = z*h + (1-z)*tanh(...) fused in epilogue (in-place)
        k_gemm<<<dim3(GB, 1), 256>>>(ph, ph, 2, 2);

        k_proj<<<(N_ + 7) / 8, 256>>>(h, Wl, bl, out + t * N_);
    }
    (void)in_sizes; (void)n_in; (void)out_size;
}

// round 4
// speedup vs baseline: 3.0136x; 3.0136x over previous
#include <cuda_runtime.h>
#include <cstdint>

#define T_ 12
#define N_ 10000
#define F_ 128
#define H_ 128
#define E_ 320000
#define NH (N_*H_)
#define WSLICE (3*F_*H_)        // 49152 floats per gate weight tensor

// ---------------- scratch (static device memory; no runtime allocation) ----------------
__device__ __align__(16) float g_Tx1[NH];
__device__ __align__(16) float g_Tx2[NH];
__device__ __align__(16) float g_Th1[NH];
__device__ __align__(16) float g_Th2[NH];
__device__ __align__(16) float g_Ts1[NH];
__device__ __align__(16) float g_Ts2[NH];
__device__ __align__(16) float g_h  [NH];
__device__ __align__(16) float g_z  [NH];
__device__ __align__(16) float g_s  [NH];
__device__ __align__(16) float g_W  [6 * WSLICE];   // tf32-rounded weights
__device__ float g_deg[N_];
__device__ int   g_cnt[N_];
__device__ int   g_rowptr[N_ + 1];
__device__ int   g_pos[E_];
__device__ int   g_col[E_];
__device__ float g_val[E_];
__device__ int   g_is64;

__device__ __forceinline__ int edge_at(const void* ei, int idx) {
    if (g_is64) return (int)((const long long*)ei)[idx];
    return ((const int*)ei)[idx];
}

// ---------------- preprocessing ----------------
// init state + detect edge dtype (int64 values < 2^32 -> odd int32 words all zero)
__global__ void k_init(const int* __restrict__ ei32) {
    int i = blockIdx.x * blockDim.x + threadIdx.x;
    if (i == 0) {
        int any_odd_nonzero = 0;
        for (int k = 1; k < 1024; k += 2) any_odd_nonzero |= (ei32[k] != 0);
        g_is64 = any_odd_nonzero ? 0 : 1;
    }
    if (i < NH) g_h[i] = 0.f;
    if (i < N_) { g_deg[i] = 0.f; g_cnt[i] = 0; }
}

__global__ void k_count(const void* __restrict__ ei) {
    int e = blockIdx.x * blockDim.x + threadIdx.x;
    if (e >= E_) return;
    int s = edge_at(ei, e);
    int d = edge_at(ei, E_ + e);
    if ((unsigned)s >= N_ || (unsigned)d >= N_) return;
    atomicAdd(&g_deg[s], 1.0f);
    g_pos[e] = atomicAdd(&g_cnt[d], 1);
}

// dinv + exclusive prefix sum (single block, 1024 threads)
__global__ void k_scan() {
    __shared__ int sh[1024];
    int tid = threadIdx.x;
    for (int i = tid; i < N_; i += 1024) {
        float d = g_deg[i];
        g_deg[i] = (d > 0.f) ? rsqrtf(d) : 0.f;
    }
    const int PER = (N_ + 1023) / 1024;
    int base = tid * PER;
    int s = 0;
    for (int i = 0; i < PER; i++) { int ix = base + i; if (ix < N_) s += g_cnt[ix]; }
    sh[tid] = s;
    __syncthreads();
    for (int off = 1; off < 1024; off <<= 1) {
        int v = (tid >= off) ? sh[tid - off] : 0;
        __syncthreads();
        if (tid >= off) sh[tid] += v;
        __syncthreads();
    }
    int run = (tid > 0) ? sh[tid - 1] : 0;
    for (int i = 0; i < PER; i++) {
        int ix = base + i;
        if (ix < N_) { g_rowptr[ix] = run; run += g_cnt[ix]; }
    }
    if (tid == 0) g_rowptr[N_] = sh[1023];
}

__global__ void k_fill(const void* __restrict__ ei) {
    int e = blockIdx.x * blockDim.x + threadIdx.x;
    if (e >= E_) return;
    int s = edge_at(ei, e);
    int d = edge_at(ei, E_ + e);
    if ((unsigned)s >= N_ || (unsigned)d >= N_) return;
    int slot = g_rowptr[d] + g_pos[e];
    g_col[slot] = s;
    g_val[slot] = -g_deg[s] * g_deg[d];
}

// pre-round all weights to tf32 (rna, unbiased) into g_W
struct W6 { const float* p[6]; };
__global__ void k_round(W6 w) {
    int idx = blockIdx.x * blockDim.x + threadIdx.x;
    if (idx >= 6 * WSLICE) return;
    int which = idx / WSLICE;
    int off = idx - which * WSLICE;
    float v = w.p[which][off];
    uint32_t r;
    asm("cvt.rna.tf32.f32 %0, %1;" : "=r"(r) : "f"(v));
    g_W[idx] = __uint_as_float(r);
}

// ---------------- graph propagation (dual) ----------------
__global__ void k_prop2(const float* __restrict__ in0, float* __restrict__ out0,
                        const float* __restrict__ sub0,
                        const float* __restrict__ in1, float* __restrict__ out1,
                        const float* __restrict__ sub1, float scale) {
    const float* in  = blockIdx.y ? in1  : in0;
    float*       out = blockIdx.y ? out1 : out0;
    const float* sub = blockIdx.y ? sub1 : sub0;
    if (!in) return;
    int n = blockIdx.x;
    int j = threadIdx.x;
    int e = g_rowptr[n], end = g_rowptr[n + 1];
    float a0 = 0.f, a1 = 0.f, a2 = 0.f, a3 = 0.f;
    for (; e + 4 <= end; e += 4) {
        int   c0 = g_col[e],     c1 = g_col[e + 1], c2 = g_col[e + 2], c3 = g_col[e + 3];
        float w0 = g_val[e],     w1 = g_val[e + 1], w2 = g_val[e + 2], w3 = g_val[e + 3];
        a0 += w0 * __ldg(in + c0 * H_ + j);
        a1 += w1 * __ldg(in + c1 * H_ + j);
        a2 += w2 * __ldg(in + c2 * H_ + j);
        a3 += w3 * __ldg(in + c3 * H_ + j);
    }
    float acc = (a0 + a1) + (a2 + a3);
    for (; e < end; e++) acc += g_val[e] * __ldg(in + g_col[e] * H_ + j);
    float r = scale * acc;
    if (sub) r -= sub[n * H_ + j];
    out[n * H_ + j] = r;
}

// ---------------- tf32 tensor-core multi-pair GEMM with fused GRU epilogues ----------------
// C[N x 128] = sum_{p<6} A_p[N x128] @ B_p[128 x128] + b0 + b1; epilogue modes:
//   0: sigmoid(v)   1: h*sigmoid(v)   2: z*h + (1-z)*tanh(v)
struct GP {
    const float* A[6];
    const float* B[6];   // tf32-pre-rounded
    const float* b0;
    const float* b1;
    const float* h;
    const float* z;
    float* out;
};

__device__ __forceinline__ float sigf(float x) { return 1.f / (1.f + expf(-x)); }

__device__ __forceinline__ void cp16(uint32_t dst, const void* src) {
    asm volatile("cp.async.cg.shared.global [%0], [%1], 16;\n" :: "r"(dst), "l"(src));
}
__device__ __forceinline__ uint32_t f2tf32(float v) {
    uint32_t r;
    asm("cvt.rna.tf32.f32 %0, %1;" : "=r"(r) : "f"(v));
    return r;
}

#define AS_STRIDE 36   // 32 + 4 pad: frag bank = lane (conflict-free)
#define BS_STRIDE 72   // 64 + 8 pad: frag bank = 8*tig + g (conflict-free)

__global__ __launch_bounds__(128) void k_gemm_tc(GP p0, GP p1, int m0, int m1) {
    const GP& P   = blockIdx.z ? p1 : p0;
    const int mode = blockIdx.z ? m1 : m0;

    __shared__ float As[2][64 * AS_STRIDE];
    __shared__ float Bs[2][32 * BS_STRIDE];

    const int tid  = threadIdx.x;
    const int wid  = tid >> 5, lane = tid & 31;
    const int g    = lane >> 2, tig = lane & 3;
    const int wm   = wid >> 1, wn = wid & 1;       // warp grid 2m x 2n
    const int bm   = blockIdx.x * 64;
    const int bn   = blockIdx.y * 64;

    float c[2][4][4];
#pragma unroll
    for (int im = 0; im < 2; im++)
#pragma unroll
        for (int it = 0; it < 4; it++)
#pragma unroll
            for (int q = 0; q < 4; q++) c[im][it][q] = 0.f;

    auto issue = [&](int s) {
        int pr = s >> 2, ch = s & 3, buf = s & 1;
        const float* Ap = P.A[pr];
        const float* Bp = P.B[pr];
        uint32_t sA = (uint32_t)__cvta_generic_to_shared(&As[buf][0]);
        uint32_t sB = (uint32_t)__cvta_generic_to_shared(&Bs[buf][0]);
#pragma unroll
        for (int i = 0; i < 4; i++) {               // A: 64x32 = 512 float4
            int fi = tid + 128 * i;
            int row = fi >> 3, c4 = fi & 7;
            int ar = bm + row; if (ar > N_ - 1) ar = N_ - 1;   // clamp (epilogue guards)
            cp16(sA + (uint32_t)(row * AS_STRIDE + c4 * 4) * 4,
                 Ap + ar * F_ + ch * 32 + c4 * 4);
        }
#pragma unroll
        for (int i = 0; i < 4; i++) {               // B: 32x64 = 512 float4
            int fi = tid + 128 * i;
            int row = fi >> 4, c4 = fi & 15;
            cp16(sB + (uint32_t)(row * BS_STRIDE + c4 * 4) * 4,
                 Bp + (ch * 32 + row) * H_ + bn + c4 * 4);
        }
        asm volatile("cp.async.commit_group;\n" ::: "memory");
    };

    issue(0);
#pragma unroll 1
    for (int s = 0; s < 24; s++) {                  // 6 pairs x 4 k-chunks of 32
        if (s + 1 < 24) {
            issue(s + 1);
            asm volatile("cp.async.wait_group 1;\n" ::: "memory");
        } else {
            asm volatile("cp.async.wait_group 0;\n" ::: "memory");
        }
        __syncthreads();
        const float* As_ = As[s & 1];
        const float* Bs_ = Bs[s & 1];
#pragma unroll
        for (int ks = 0; ks < 4; ks++) {
            const int k = ks * 8;
            uint32_t a[2][4];
#pragma unroll
            for (int im = 0; im < 2; im++) {
                int r0 = wm * 32 + im * 16 + g;
                a[im][0] = f2tf32(As_[r0 * AS_STRIDE + k + tig]);
                a[im][1] = f2tf32(As_[(r0 + 8) * AS_STRIDE + k + tig]);
                a[im][2] = f2tf32(As_[r0 * AS_STRIDE + k + tig + 4]);
                a[im][3] = f2tf32(As_[(r0 + 8) * AS_STRIDE + k + tig + 4]);
            }
            uint32_t b[4][2];
#pragma unroll
            for (int it = 0; it < 4; it++) {
                int cb = wn * 32 + it * 8 + g;
                b[it][0] = __float_as_uint(Bs_[(k + tig) * BS_STRIDE + cb]);
                b[it][1] = __float_as_uint(Bs_[(k + tig + 4) * BS_STRIDE + cb]);
            }
#pragma unroll
            for (int im = 0; im < 2; im++)
#pragma unroll
                for (int it = 0; it < 4; it++) {
                    asm volatile(
                        "mma.sync.aligned.m16n8k8.row.col.f32.tf32.tf32.f32 "
                        "{%0,%1,%2,%3}, {%4,%5,%6,%7}, {%8,%9}, {%0,%1,%2,%3};\n"
                        : "+f"(c[im][it][0]), "+f"(c[im][it][1]),
                          "+f"(c[im][it][2]), "+f"(c[im][it][3])
                        : "r"(a[im][0]), "r"(a[im][1]), "r"(a[im][2]), "r"(a[im][3]),
                          "r"(b[it][0]), "r"(b[it][1]));
                }
        }
        __syncthreads();
    }

    // epilogue
#pragma unroll
    for (int im = 0; im < 2; im++) {
        int rbase = bm + wm * 32 + im * 16 + g;
#pragma unroll
        for (int half = 0; half < 2; half++) {
            int row = rbase + half * 8;
            if (row >= N_) continue;
#pragma unroll
            for (int it = 0; it < 4; it++) {
#pragma unroll
                for (int q = 0; q < 2; q++) {
                    int col = bn + wn * 32 + it * 8 + 2 * tig + q;
                    float v = c[im][it][half * 2 + q] + __ldg(P.b0 + col) + __ldg(P.b1 + col);
                    int idx = row * H_ + col;
                    float o;
                    if (mode == 0)      o = sigf(v);
                    else if (mode == 1) o = P.h[idx] * sigf(v);
                    else { float zz = P.z[idx]; o = zz * P.h[idx] + (1.f - zz) * tanhf(v); }
                    P.out[idx] = o;
                }
            }
        }
    }
}

// ---------------- output projection ----------------
__global__ void k_proj(const float* __restrict__ h, const float* __restrict__ Wl,
                       const float* __restrict__ bl, float* __restrict__ out) {
    int n = blockIdx.x * 8 + (threadIdx.x >> 5);
    if (n >= N_) return;
    int lane = threadIdx.x & 31;
    float4 a = *(const float4*)(h + n * H_ + lane * 4);
    float4 w = *(const float4*)(Wl + lane * 4);
    float s = a.x * w.x + a.y * w.y + a.z * w.z + a.w * w.w;
#pragma unroll
    for (int o = 16; o; o >>= 1) s += __shfl_down_sync(0xffffffffu, s, o);
    if (lane == 0) out[n] = s + bl[0];
}

// ---------------- driver ----------------
extern "C" void kernel_launch(void* const* d_in, const int* in_sizes, int n_in,
                              void* d_out, int out_size) {
    const float* x_seq = (const float*)d_in[0];
    const void*  ei    = d_in[1];
    const float* Wxz = (const float*)d_in[2];  const float* bxz = (const float*)d_in[3];
    const float* Whz = (const float*)d_in[4];  const float* bhz = (const float*)d_in[5];
    const float* Wxr = (const float*)d_in[6];  const float* bxr = (const float*)d_in[7];
    const float* Whr = (const float*)d_in[8];  const float* bhr = (const float*)d_in[9];
    const float* Wxh = (const float*)d_in[10]; const float* bxh = (const float*)d_in[11];
    const float* Whh = (const float*)d_in[12]; const float* bhh = (const float*)d_in[13];
    const float* Wl  = (const float*)d_in[14]; const float* bl  = (const float*)d_in[15];
    float* out = (float*)d_out;

    float *Tx1, *Tx2, *Th1, *Th2, *Ts1, *Ts2, *h, *z, *s, *gW;
    cudaGetSymbolAddress((void**)&Tx1, g_Tx1);
    cudaGetSymbolAddress((void**)&Tx2, g_Tx2);
    cudaGetSymbolAddress((void**)&Th1, g_Th1);
    cudaGetSymbolAddress((void**)&Th2, g_Th2);
    cudaGetSymbolAddress((void**)&Ts1, g_Ts1);
    cudaGetSymbolAddress((void**)&Ts2, g_Ts2);
    cudaGetSymbolAddress((void**)&h,   g_h);
    cudaGetSymbolAddress((void**)&z,   g_z);
    cudaGetSymbolAddress((void**)&s,   g_s);
    cudaGetSymbolAddress((void**)&gW,  g_W);

    // preprocessing (5 launches -> ncu's skip-5 capture lands on first hot k_prop2)
    k_init <<<(NH + 255) / 256, 256>>>((const int*)ei);
    k_count<<<(E_ + 255) / 256, 256>>>(ei);
    k_scan <<<1, 1024>>>();
    k_fill <<<(E_ + 255) / 256, 256>>>(ei);
    W6 w6; w6.p[0] = Wxz; w6.p[1] = Whz; w6.p[2] = Wxr; w6.p[3] = Whr; w6.p[4] = Wxh; w6.p[5] = Whh;
    k_round<<<(6 * WSLICE + 255) / 256, 256>>>(w6);

    const int WK = F_ * H_;
    const int GB = (N_ + 63) / 64;        // 157 row tiles

    for (int t = 0; t < T_; t++) {
        const float* xt = x_seq + (size_t)t * N_ * F_;

        k_prop2<<<dim3(N_, 2), H_>>>(xt,  Tx1, nullptr, h,   Th1, nullptr, 1.f);
        k_prop2<<<dim3(N_, 2), H_>>>(Tx1, Tx2, xt,      Th1, Th2, h,       2.f);

        GP pz, pr, ph;
        const float* Axs[6] = { xt, Tx1, Tx2, h, Th1, Th2 };
        for (int i = 0; i < 6; i++) { pz.A[i] = Axs[i]; pr.A[i] = Axs[i]; }
        for (int k = 0; k < 3; k++) {
            pz.B[k] = gW + 0 * WSLICE + k * WK; pz.B[3 + k] = gW + 1 * WSLICE + k * WK;
            pr.B[k] = gW + 2 * WSLICE + k * WK; pr.B[3 + k] = gW + 3 * WSLICE + k * WK;
        }
        pz.b0 = bxz; pz.b1 = bhz; pz.out = z; pz.h = nullptr; pz.z = nullptr;
        pr.b0 = bxr; pr.b1 = bhr; pr.out = s; pr.h = h;       pr.z = nullptr;
        k_gemm_tc<<<dim3(GB, 2, 2), 128>>>(pz, pr, 0, 1);

        k_prop2<<<dim3(N_, 1), H_>>>(s,   Ts1, nullptr, nullptr, nullptr, nullptr, 1.f);
        k_prop2<<<dim3(N_, 1), H_>>>(Ts1, Ts2, s,       nullptr, nullptr, nullptr, 2.f);

        const float* Ahs[6] = { xt, Tx1, Tx2, s, Ts1, Ts2 };
        for (int i = 0; i < 6; i++) ph.A[i] = Ahs[i];
        for (int k = 0; k < 3; k++) {
            ph.B[k] = gW + 4 * WSLICE + k * WK; ph.B[3 + k] = gW + 5 * WSLICE + k * WK;
        }
        ph.b0 = bxh; ph.b1 = bhh; ph.out = h; ph.h = h; ph.z = z;
        k_gemm_tc<<<dim3(GB, 2, 1), 128>>>(ph, ph, 2, 2);

        k_proj<<<(N_ + 7) / 8, 256>>>(h, Wl, bl, out + t * N_);
    }
    (void)in_sizes; (void)n_in; (void)out_size;
}